// round 1
// baseline (speedup 1.0000x reference)
#include <cuda_runtime.h>
#include <math.h>
#include <stdint.h>

#define L_TOK   2048
#define DMODEL  512
#define DINNER  1024
#define DSTATE  16
#define DTRANK  32
#define INDIM   1024
#define NLAYER  2
#define NCHUNK  16
#define CHUNK   128   /* L_TOK / NCHUNK */

// ---------------- scratch (device globals; no allocation) ----------------
__device__ float g_h    [L_TOK * DMODEL];
__device__ float g_hn   [L_TOK * DMODEL];
__device__ float g_xz   [L_TOK * 2 * DINNER];
__device__ float g_u    [L_TOK * DINNER];
__device__ float g_dbc  [L_TOK * 80];
__device__ float g_delta[L_TOK * DINNER];
__device__ float g_y    [L_TOK * DINNER];
__device__ float g_P    [NCHUNK * DINNER * DSTATE];
__device__ float g_S    [NCHUNK * DINNER * DSTATE];
__device__ float g_init [NCHUNK * DINNER * DSTATE];
__device__ float g_scores[L_TOK];

// ---------------- generic tiled fp32 GEMM: C[M,N] = A[M,K] @ B[K,N] ------
enum { EPI_NONE = 0, EPI_GELU = 1, EPI_SOFTPLUS = 2, EPI_ADD = 3 };

template <int EPI>
__global__ __launch_bounds__(256)
void gemm_kernel(int M, int N, int K,
                 const float* __restrict__ A, int lda,
                 const float* __restrict__ B, int ldb,
                 float* __restrict__ C, int ldc,
                 const float* __restrict__ bias)
{
    __shared__ float sA[16][68];   // [k][m], pad to 68 (float4-aligned, low conflict)
    __shared__ float sB[16][68];   // [k][n]

    const int bm  = blockIdx.y * 64;
    const int bn  = blockIdx.x * 64;
    const int tid = threadIdx.x;
    const int tm  = (tid >> 4) << 2;   // 0..60
    const int tn  = (tid & 15) << 2;   // 0..60

    float acc[4][4];
#pragma unroll
    for (int i = 0; i < 4; i++)
#pragma unroll
        for (int j = 0; j < 4; j++) acc[i][j] = 0.f;

    for (int k0 = 0; k0 < K; k0 += 16) {
#pragma unroll
        for (int it = 0; it < 4; it++) {
            int i  = tid + it * 256;
            int m  = i >> 4, kk = i & 15;
            int gm = bm + m, gk = k0 + kk;
            sA[kk][m] = (gm < M && gk < K) ? A[(size_t)gm * lda + gk] : 0.f;
        }
#pragma unroll
        for (int it = 0; it < 4; it++) {
            int i  = tid + it * 256;
            int kk = i >> 6, n = i & 63;
            int gk = k0 + kk, gn = bn + n;
            sB[kk][n] = (gk < K && gn < N) ? B[(size_t)gk * ldb + gn] : 0.f;
        }
        __syncthreads();
#pragma unroll
        for (int kk = 0; kk < 16; kk++) {
            float4 av = *reinterpret_cast<const float4*>(&sA[kk][tm]);
            float4 bv = *reinterpret_cast<const float4*>(&sB[kk][tn]);
            float a[4] = {av.x, av.y, av.z, av.w};
            float b[4] = {bv.x, bv.y, bv.z, bv.w};
#pragma unroll
            for (int i = 0; i < 4; i++)
#pragma unroll
                for (int j = 0; j < 4; j++)
                    acc[i][j] = fmaf(a[i], b[j], acc[i][j]);
        }
        __syncthreads();
    }

#pragma unroll
    for (int i = 0; i < 4; i++) {
        int gm = bm + tm + i;
        if (gm >= M) continue;
#pragma unroll
        for (int j = 0; j < 4; j++) {
            int gn = bn + tn + j;
            if (gn >= N) continue;
            float v = acc[i][j];
            if (EPI == EPI_GELU) {
                v += bias[gn];
                v = 0.5f * v * (1.f + erff(v * 0.70710678118654752f));
            } else if (EPI == EPI_SOFTPLUS) {
                v += bias[gn];
                v = (v > 15.f) ? v : log1pf(expf(v));
            } else if (EPI == EPI_ADD) {
                v += C[(size_t)gm * ldc + gn];
            }
            C[(size_t)gm * ldc + gn] = v;
        }
    }
}

// ---------------- pos embedding add ----------------
__global__ void posadd_kernel(float* __restrict__ h,
                              const float* __restrict__ pos,
                              const float* __restrict__ pos_w,
                              const float* __restrict__ pos_b)
{
    int idx = blockIdx.x * blockDim.x + threadIdx.x;
    if (idx >= L_TOK * DMODEL) return;
    int t = idx >> 9, d = idx & 511;
    h[idx] += pos[2 * t] * pos_w[d] + pos[2 * t + 1] * pos_w[DMODEL + d] + pos_b[d];
}

// ---------------- block reduce helper ----------------
__device__ __forceinline__ float block_reduce_sum(float v, float* sred)
{
    int tid = threadIdx.x;
#pragma unroll
    for (int o = 16; o > 0; o >>= 1) v += __shfl_down_sync(0xffffffff, v, o);
    if ((tid & 31) == 0) sred[tid >> 5] = v;
    __syncthreads();
    float r;
    if (tid < 32) {
        int nw = blockDim.x >> 5;
        r = (tid < nw) ? sred[tid] : 0.f;
#pragma unroll
        for (int o = 16; o > 0; o >>= 1) r += __shfl_down_sync(0xffffffff, r, o);
        if (tid == 0) sred[0] = r;
    }
    __syncthreads();
    r = sred[0];
    __syncthreads();
    return r;
}

// ---------------- RMSNorm (per row, D=512) ----------------
__global__ void rmsnorm_kernel(const float* __restrict__ h,
                               const float* __restrict__ w,
                               float* __restrict__ out)
{
    __shared__ float sred[32];
    int t = blockIdx.x;
    const float* row = h + (size_t)t * DMODEL;
    float ss = 0.f;
    for (int d = threadIdx.x; d < DMODEL; d += blockDim.x) {
        float v = row[d];
        ss = fmaf(v, v, ss);
    }
    float tot = block_reduce_sum(ss, sred);
    float sc  = rsqrtf(tot * (1.f / DMODEL) + 1e-5f);
    for (int d = threadIdx.x; d < DMODEL; d += blockDim.x)
        out[(size_t)t * DMODEL + d] = row[d] * w[d] * sc;
}

// ---------------- LayerNorm ----------------
__global__ void layernorm_kernel(const float* __restrict__ h,
                                 const float* __restrict__ w,
                                 const float* __restrict__ b,
                                 float* __restrict__ out)
{
    __shared__ float sred[32];
    int t = blockIdx.x;
    const float* row = h + (size_t)t * DMODEL;
    float s = 0.f, ss = 0.f;
    for (int d = threadIdx.x; d < DMODEL; d += blockDim.x) {
        float v = row[d];
        s += v;
        ss = fmaf(v, v, ss);
    }
    float tot  = block_reduce_sum(s, sred);
    float tot2 = block_reduce_sum(ss, sred);
    float mu  = tot * (1.f / DMODEL);
    float var = tot2 * (1.f / DMODEL) - mu * mu;
    float sc  = rsqrtf(var + 1e-5f);
    for (int d = threadIdx.x; d < DMODEL; d += blockDim.x)
        out[(size_t)t * DMODEL + d] = (row[d] - mu) * sc * w[d] + b[d];
}

// ---------------- depthwise causal conv1d + SiLU ----------------
__global__ void conv_silu_kernel(const float* __restrict__ xz,
                                 const float* __restrict__ cw,
                                 const float* __restrict__ cb,
                                 float* __restrict__ u)
{
    int idx = blockIdx.x * blockDim.x + threadIdx.x;
    if (idx >= L_TOK * DINNER) return;
    int t = idx >> 10, c = idx & 1023;
    const float* w = cw + c * 4;
    float acc = cb[c];
#pragma unroll
    for (int k = 0; k < 4; k++) {
        int tt = t - 3 + k;
        if (tt >= 0) acc = fmaf(w[k], xz[(size_t)tt * (2 * DINNER) + c], acc);
    }
    u[idx] = acc / (1.f + __expf(-acc));
}

// ---------------- scan pass A: per-chunk (prod dA, state-from-zero) -------
__global__ __launch_bounds__(128)
void scan_a_kernel(const float* __restrict__ delta,
                   const float* __restrict__ u,
                   const float* __restrict__ dbc,
                   const float* __restrict__ A_log,
                   float* __restrict__ Pout,
                   float* __restrict__ Sout)
{
    __shared__ float sB[CHUNK][DSTATE];
    int e  = blockIdx.y * 128 + threadIdx.x;
    int c  = blockIdx.x;
    int t0 = c * CHUNK;
    for (int i = threadIdx.x; i < CHUNK * DSTATE; i += 128) {
        int tl = i >> 4, n = i & 15;
        sB[tl][n] = dbc[(size_t)(t0 + tl) * 80 + 32 + n];
    }
    __syncthreads();
    float Aneg[DSTATE], h[DSTATE], P[DSTATE];
#pragma unroll
    for (int n = 0; n < DSTATE; n++) {
        Aneg[n] = -expf(A_log[(size_t)e * DSTATE + n]);
        h[n] = 0.f;
        P[n] = 1.f;
    }
    for (int tl = 0; tl < CHUNK; tl++) {
        int   t  = t0 + tl;
        float dl = delta[(size_t)t * DINNER + e];
        float ul = u[(size_t)t * DINNER + e];
        float du = dl * ul;
#pragma unroll
        for (int n = 0; n < DSTATE; n++) {
            float dA = __expf(dl * Aneg[n]);
            h[n] = fmaf(dA, h[n], du * sB[tl][n]);
            P[n] *= dA;
        }
    }
    size_t base = ((size_t)c * DINNER + e) * DSTATE;
#pragma unroll
    for (int n = 0; n < DSTATE; n++) {
        Sout[base + n] = h[n];
        Pout[base + n] = P[n];
    }
}

// ---------------- scan pass B: compose chunk prefixes ----------------
__global__ void scan_b_kernel(const float* __restrict__ P,
                              const float* __restrict__ S,
                              float* __restrict__ init)
{
    int e = blockIdx.x * blockDim.x + threadIdx.x;
    if (e >= DINNER) return;
    float h[DSTATE];
#pragma unroll
    for (int n = 0; n < DSTATE; n++) h[n] = 0.f;
    for (int c = 0; c < NCHUNK; c++) {
        size_t base = ((size_t)c * DINNER + e) * DSTATE;
#pragma unroll
        for (int n = 0; n < DSTATE; n++) init[base + n] = h[n];
#pragma unroll
        for (int n = 0; n < DSTATE; n++)
            h[n] = fmaf(P[base + n], h[n], S[base + n]);
    }
}

// ---------------- scan pass C: replay with init, emit y*silu(z) ----------
__global__ __launch_bounds__(128)
void scan_c_kernel(const float* __restrict__ delta,
                   const float* __restrict__ u,
                   const float* __restrict__ dbc,
                   const float* __restrict__ A_log,
                   const float* __restrict__ Dd,
                   const float* __restrict__ init,
                   const float* __restrict__ xz,
                   float* __restrict__ y)
{
    __shared__ float sB[CHUNK][DSTATE];
    __shared__ float sC[CHUNK][DSTATE];
    int e  = blockIdx.y * 128 + threadIdx.x;
    int c  = blockIdx.x;
    int t0 = c * CHUNK;
    for (int i = threadIdx.x; i < CHUNK * DSTATE; i += 128) {
        int tl = i >> 4, n = i & 15;
        sB[tl][n] = dbc[(size_t)(t0 + tl) * 80 + 32 + n];
        sC[tl][n] = dbc[(size_t)(t0 + tl) * 80 + 48 + n];
    }
    __syncthreads();
    float Aneg[DSTATE], h[DSTATE];
    size_t base = ((size_t)c * DINNER + e) * DSTATE;
#pragma unroll
    for (int n = 0; n < DSTATE; n++) {
        Aneg[n] = -expf(A_log[(size_t)e * DSTATE + n]);
        h[n]    = init[base + n];
    }
    float Dde = Dd[e];
    for (int tl = 0; tl < CHUNK; tl++) {
        int   t  = t0 + tl;
        float dl = delta[(size_t)t * DINNER + e];
        float ul = u[(size_t)t * DINNER + e];
        float du = dl * ul;
        float acc = Dde * ul;
#pragma unroll
        for (int n = 0; n < DSTATE; n++) {
            float dA = __expf(dl * Aneg[n]);
            h[n] = fmaf(dA, h[n], du * sB[tl][n]);
            acc  = fmaf(h[n], sC[tl][n], acc);
        }
        float zv = xz[(size_t)t * (2 * DINNER) + DINNER + e];
        float sz = zv / (1.f + __expf(-zv));
        y[(size_t)t * DINNER + e] = acc * sz;
    }
}

// ---------------- attention scores: s[t] = tanh(h@W1+b1)@W2 + b2 ----------
__global__ __launch_bounds__(128)
void attn_kernel(const float* __restrict__ hn,
                 const float* __restrict__ w1,
                 const float* __restrict__ b1,
                 const float* __restrict__ w2,
                 const float* __restrict__ b2,
                 float* __restrict__ scores)
{
    __shared__ float sh[DMODEL];
    __shared__ float red[128];
    int t   = blockIdx.x;
    int tid = threadIdx.x;
    for (int d = tid; d < DMODEL; d += 128) sh[d] = hn[(size_t)t * DMODEL + d];
    __syncthreads();
    float dot = 0.f;
    for (int k = 0; k < DMODEL; k++)
        dot = fmaf(sh[k], w1[(size_t)k * 128 + tid], dot);
    float v = tanhf(dot + b1[tid]) * w2[tid];
    red[tid] = v;
    __syncthreads();
    for (int s = 64; s > 0; s >>= 1) {
        if (tid < s) red[tid] += red[tid + s];
        __syncthreads();
    }
    if (tid == 0) scores[t] = red[0] + b2[0];
}

// ---------------- softmax pooling + classifier (single block) -------------
__global__ __launch_bounds__(512)
void final_kernel(const float* __restrict__ hn,
                  const float* __restrict__ scores,
                  const float* __restrict__ cls_w,
                  const float* __restrict__ cls_b,
                  float* __restrict__ out)
{
    __shared__ float sw[L_TOK];
    __shared__ float red[512];
    int tid = threadIdx.x;

    float mx = -1e30f;
    for (int i = tid; i < L_TOK; i += 512) {
        float s = scores[i];
        sw[i] = s;
        mx = fmaxf(mx, s);
    }
    red[tid] = mx;
    __syncthreads();
    for (int s = 256; s > 0; s >>= 1) {
        if (tid < s) red[tid] = fmaxf(red[tid], red[tid + s]);
        __syncthreads();
    }
    mx = red[0];
    __syncthreads();

    float lsum = 0.f;
    for (int i = tid; i < L_TOK; i += 512) {
        float ev = expf(sw[i] - mx);
        sw[i] = ev;
        lsum += ev;
    }
    red[tid] = lsum;
    __syncthreads();
    for (int s = 256; s > 0; s >>= 1) {
        if (tid < s) red[tid] += red[tid + s];
        __syncthreads();
    }
    float tot = red[0];
    __syncthreads();

    float accp = 0.f;
    for (int t = 0; t < L_TOK; t++)
        accp = fmaf(sw[t], hn[(size_t)t * DMODEL + tid], accp);
    accp /= tot;

#pragma unroll
    for (int c = 0; c < 2; c++) {
        red[tid] = accp * cls_w[tid * 2 + c];
        __syncthreads();
        for (int s = 256; s > 0; s >>= 1) {
            if (tid < s) red[tid] += red[tid + s];
            __syncthreads();
        }
        if (tid == 0) out[c] = red[0] + cls_b[c];
        __syncthreads();
    }
}

// ---------------- host launcher ----------------
extern "C" void kernel_launch(void* const* d_in, const int* in_sizes, int n_in,
                              void* d_out, int out_size)
{
    const float* x       = (const float*)d_in[0];
    const float* pos     = (const float*)d_in[1];
    const float* fc1_w   = (const float*)d_in[2];
    const float* fc1_b   = (const float*)d_in[3];
    const float* pos_w   = (const float*)d_in[4];
    const float* pos_b   = (const float*)d_in[5];
    const float* in_proj = (const float*)d_in[6];
    const float* conv_w  = (const float*)d_in[7];
    const float* conv_b  = (const float*)d_in[8];
    const float* x_proj  = (const float*)d_in[9];
    const float* dt_w    = (const float*)d_in[10];
    const float* dt_b    = (const float*)d_in[11];
    const float* A_log   = (const float*)d_in[12];
    const float* Dd      = (const float*)d_in[13];
    const float* out_w   = (const float*)d_in[14];
    const float* rms_w   = (const float*)d_in[15];
    const float* norm_w  = (const float*)d_in[16];
    const float* norm_b  = (const float*)d_in[17];
    const float* attn_w1 = (const float*)d_in[18];
    const float* attn_b1 = (const float*)d_in[19];
    const float* attn_w2 = (const float*)d_in[20];
    const float* attn_b2 = (const float*)d_in[21];
    const float* cls_w   = (const float*)d_in[22];
    const float* cls_b   = (const float*)d_in[23];

    float *p_h, *p_hn, *p_xz, *p_u, *p_dbc, *p_delta, *p_y;
    float *p_P, *p_S, *p_init, *p_scores;
    cudaGetSymbolAddress((void**)&p_h,      g_h);
    cudaGetSymbolAddress((void**)&p_hn,     g_hn);
    cudaGetSymbolAddress((void**)&p_xz,     g_xz);
    cudaGetSymbolAddress((void**)&p_u,      g_u);
    cudaGetSymbolAddress((void**)&p_dbc,    g_dbc);
    cudaGetSymbolAddress((void**)&p_delta,  g_delta);
    cudaGetSymbolAddress((void**)&p_y,      g_y);
    cudaGetSymbolAddress((void**)&p_P,      g_P);
    cudaGetSymbolAddress((void**)&p_S,      g_S);
    cudaGetSymbolAddress((void**)&p_init,   g_init);
    cudaGetSymbolAddress((void**)&p_scores, g_scores);

    // fc1 + GELU
    gemm_kernel<EPI_GELU><<<dim3(8, 32), 256>>>(
        L_TOK, DMODEL, INDIM, x, INDIM, fc1_w, DMODEL, p_h, DMODEL, fc1_b);
    // + positional embedding
    posadd_kernel<<<(L_TOK * DMODEL) / 256, 256>>>(p_h, pos, pos_w, pos_b);

    for (int l = 0; l < NLAYER; l++) {
        rmsnorm_kernel<<<L_TOK, 256>>>(p_h, rms_w + (size_t)l * DMODEL, p_hn);

        gemm_kernel<EPI_NONE><<<dim3(32, 32), 256>>>(
            L_TOK, 2 * DINNER, DMODEL,
            p_hn, DMODEL,
            in_proj + (size_t)l * DMODEL * 2 * DINNER, 2 * DINNER,
            p_xz, 2 * DINNER, nullptr);

        conv_silu_kernel<<<(L_TOK * DINNER) / 256, 256>>>(
            p_xz, conv_w + (size_t)l * DINNER * 4, conv_b + (size_t)l * DINNER, p_u);

        gemm_kernel<EPI_NONE><<<dim3(2, 32), 256>>>(
            L_TOK, 80, DINNER,
            p_u, DINNER,
            x_proj + (size_t)l * DINNER * 80, 80,
            p_dbc, 80, nullptr);

        gemm_kernel<EPI_SOFTPLUS><<<dim3(16, 32), 256>>>(
            L_TOK, DINNER, DTRANK,
            p_dbc, 80,
            dt_w + (size_t)l * DTRANK * DINNER, DINNER,
            p_delta, DINNER, dt_b + (size_t)l * DINNER);

        scan_a_kernel<<<dim3(NCHUNK, DINNER / 128), 128>>>(
            p_delta, p_u, p_dbc, A_log + (size_t)l * DINNER * DSTATE, p_P, p_S);
        scan_b_kernel<<<DINNER / 256, 256>>>(p_P, p_S, p_init);
        scan_c_kernel<<<dim3(NCHUNK, DINNER / 128), 128>>>(
            p_delta, p_u, p_dbc, A_log + (size_t)l * DINNER * DSTATE,
            Dd + (size_t)l * DINNER, p_init, p_xz, p_y);

        gemm_kernel<EPI_ADD><<<dim3(8, 32), 256>>>(
            L_TOK, DMODEL, DINNER,
            p_y, DINNER,
            out_w + (size_t)l * DINNER * DMODEL, DMODEL,
            p_h, DMODEL, nullptr);
    }

    layernorm_kernel<<<L_TOK, 256>>>(p_h, norm_w, norm_b, p_hn);
    attn_kernel<<<L_TOK, 128>>>(p_hn, attn_w1, attn_b1, attn_w2, attn_b2, p_scores);
    final_kernel<<<1, 512>>>(p_hn, p_scores, cls_w, cls_b, (float*)d_out);
}